// round 9
// baseline (speedup 1.0000x reference)
#include <cuda_runtime.h>
#include <cuda_fp16.h>

#define NBATCH 2
#define PPB (128*128*128)       // points per batch
#define NB 64
#define BPB 148                 // blocks per batch (2 blocks/SM)
#define TOTB (BPB * NBATCH)     // 296
#define THREADS 256

// Plane layout: 2 parity planes, each 66 stored rows x 34 half2 pairs.
// Stored row = logical row + 1 (rows 0 and 65 are guards).
// Pair q in plane p: lo accumulates col (2q-2+p) [wym&wyp taps], hi col (2q-1+p) [wy0].
#define PROWS 66
#define PPAIR 34
#define PS (PROWS * PPAIR)      // 2244 half2 per plane

// Scratch (zero at module load; the last block resets everything each replay)
__device__ float g_hist[NBATCH][NB * NB];
__device__ float g_total[NBATCH];
__device__ unsigned int g_ticket;

__global__ __launch_bounds__(THREADS) void mi_kernel(const float* __restrict__ x,
                                                     const float* __restrict__ y,
                                                     float* __restrict__ out) {
    __shared__ __half2 sh2[2 * PS];
    __shared__ float red_a[8], red_b[8];
    __shared__ float s_py[NB];
    __shared__ float s_res[NBATCH];
    __shared__ unsigned int s_last;
    const int n = blockIdx.y;
    const int t = threadIdx.x;
    const int lane = t & 31;
    const int w = t >> 5;

    for (int i = t; i < 2 * PS; i += THREADS) ((unsigned int*)sh2)[i] = 0u;
    __syncthreads();

    // K2 = DELTA^2/(2 sigma^2); constant scales dropped (cancel under norm).
    const float K2 = (float)( (1.0/63.0)*(1.0/63.0)
                     / (2.0 * (0.015625/2.3548200450309493) * (0.015625/2.3548200450309493)) );

    const float4* x4 = (const float4*)(x + (size_t)n * PPB);
    const float4* y4 = (const float4*)(y + (size_t)n * PPB);
    const int nvec = PPB / 4;
    const int stride = BPB * THREADS;

    for (int v = blockIdx.x * THREADS + t; v < nvec; v += stride) {
        float4 xv = x4[v];
        float4 yv = y4[v];
        float xs[4] = {xv.x, xv.y, xv.z, xv.w};
        float ys[4] = {yv.x, yv.y, yv.z, yv.w};
        #pragma unroll
        for (int e = 0; e < 4; e++) {
            float fx = xs[e] * 63.0f;
            int ix = __float2int_rn(fx);
            float ux = fx - (float)ix;
            float Ax = -K2 * ux * ux;
            float Bx = (2.0f * K2) * ux;
            float wx0 = __expf(Ax);
            float wxm = __expf(Ax - Bx - K2);
            float wxp = __expf(Ax + Bx - K2);
            float fy = ys[e] * 63.0f;
            int iy = __float2int_rn(fy);
            float uy = fy - (float)iy;
            float Ay = -K2 * uy * uy;
            float By = (2.0f * K2) * uy;
            float wy0 = __expf(Ay);
            float wym = __expf(Ay - By - K2);
            float wyp = __expf(Ay + By - K2);

            int par = iy & 1;
            int q0 = ((iy - 1) >> 1) + 1;              // 0..32
            int base = par * PS + ix * PPAIR + q0;     // guards absorb edges

            __half2 hy0 = __floats2half2_rn(wym, wy0);
            __half2 hy1 = __floats2half2_rn(wyp, 0.0f);
            __half2 hxm = __float2half2_rn(wxm);
            __half2 hx0 = __float2half2_rn(wx0);
            __half2 hxp = __float2half2_rn(wxp);

            atomicAdd(&sh2[base],               __hmul2(hxm, hy0));
            atomicAdd(&sh2[base + 1],           __hmul2(hxm, hy1));
            atomicAdd(&sh2[base + PPAIR],       __hmul2(hx0, hy0));
            atomicAdd(&sh2[base + PPAIR + 1],   __hmul2(hx0, hy1));
            atomicAdd(&sh2[base + 2*PPAIR],     __hmul2(hxp, hy0));
            atomicAdd(&sh2[base + 2*PPAIR + 1], __hmul2(hxp, hy1));
        }
    }

    __syncthreads();
    // ---- de-plane flush to global + block partial total (interior only) ----
    float s = 0.0f;
    for (int i = t; i < NB * NB; i += THREADS) {
        int r = i >> 6, c = i & 63;
        int sr = (r + 1) * PPAIR;
        float val;
        if (c & 1) {
            int q = (c + 1) >> 1;
            val = __low2float(sh2[sr + q]) + __high2float(sh2[PS + sr + q]);
        } else {
            val = __low2float(sh2[PS + sr + (c >> 1) + 1])
                + __high2float(sh2[sr + (c >> 1)]);
        }
        s += val;
        atomicAdd(&g_hist[n][i], val);
    }
    #pragma unroll
    for (int o = 16; o; o >>= 1) s += __shfl_down_sync(0xffffffffu, s, o);
    if (lane == 0) red_a[w] = s;
    __syncthreads();
    if (t == 0) {
        float tt = 0.0f;
        #pragma unroll
        for (int i = 0; i < 8; i++) tt += red_a[i];
        atomicAdd(&g_total[n], tt);
    }

    // ---- grid-wide ticket; last block finishes the reduction ----
    __threadfence();
    __syncthreads();
    if (t == 0) s_last = atomicInc(&g_ticket, TOTB - 1);   // wraps to 0
    __syncthreads();
    if (s_last != TOTB - 1) return;
    __threadfence();

    const float EPS = 1e-5f;
    for (int nn = 0; nn < NBATCH; nn++) {
        const float* h = g_hist[nn];
        const float inv = 1.0f / (g_total[nn] + EPS);
        if (t < NB) s_py[t] = 0.0f;
        __syncthreads();

        // warp w owns rows [8w, 8w+8); lane owns cols lane & lane+32
        float ej = 0.0f, em = 0.0f, col0 = 0.0f, col1 = 0.0f;
        #pragma unroll
        for (int r8 = 0; r8 < 8; r8++) {
            int r = w * 8 + r8;
            float c0 = h[r * NB + lane];
            float c1 = h[r * NB + lane + 32];
            float p0 = c0 * inv, p1 = c1 * inv;
            ej += p0 * __logf(p0 + EPS) + p1 * __logf(p1 + EPS);
            col0 += c0; col1 += c1;
            float rs = c0 + c1;
            #pragma unroll
            for (int o = 16; o; o >>= 1) rs += __shfl_down_sync(0xffffffffu, rs, o);
            if (lane == 0) {
                float px = rs * inv;
                em += px * __logf(px + EPS);
            }
        }
        atomicAdd(&s_py[lane], col0);
        atomicAdd(&s_py[lane + 32], col1);
        #pragma unroll
        for (int o = 16; o; o >>= 1) ej += __shfl_down_sync(0xffffffffu, ej, o);
        if (lane == 0) { red_a[w] = ej; red_b[w] = em; }
        __syncthreads();                 // s_py complete; red_a/red_b written

        // py entropy: t<64, warps 0-1
        float epy = 0.0f;
        if (t < NB) {
            float v = s_py[t] * inv;
            epy = v * __logf(v + EPS);
        }
        #pragma unroll
        for (int o = 16; o; o >>= 1) epy += __shfl_down_sync(0xffffffffu, epy, o);
        if (lane == 0 && w < 2) s_py[w] = epy;   // reuse s_py[0..1] as scratch
        __syncthreads();

        if (t == 0) {
            float sej = 0.0f, sem = 0.0f;
            #pragma unroll
            for (int i = 0; i < 8; i++) { sej += red_a[i]; sem += red_b[i]; }
            float sepy = s_py[0] + s_py[1];
            s_res[nn] = (sem + sepy) / sej;      // (ent_x+ent_y)/ent_joint
            g_total[nn] = 0.0f;                  // reset for next replay
        }

        // zero own rows for next replay (each warp read only its own rows)
        #pragma unroll
        for (int r8 = 0; r8 < 8; r8++) {
            int r = w * 8 + r8;
            ((float*)g_hist[nn])[r * NB + lane] = 0.0f;
            ((float*)g_hist[nn])[r * NB + lane + 32] = 0.0f;
        }
        __syncthreads();
    }

    if (t == 0) out[0] = -0.5f * (s_res[0] + s_res[1]);
}

extern "C" void kernel_launch(void* const* d_in, const int* in_sizes, int n_in,
                              void* d_out, int out_size) {
    const float* x = (const float*)d_in[0];
    const float* y = (const float*)d_in[1];
    float* out = (float*)d_out;

    mi_kernel<<<dim3(BPB, NBATCH), THREADS>>>(x, y, out);
}

// round 10
// speedup vs baseline: 1.1672x; 1.1672x over previous
#include <cuda_runtime.h>
#include <cuda_fp16.h>

#define NBATCH 2
#define PPB (128*128*128)       // points per batch
#define NB 64
#define BPB 148                 // blocks per batch
#define TOTB (BPB * NBATCH)     // 296 blocks, 512 threads: 32 warps/SM
#define THREADS 512

// Plane layout: 2 parity planes, each 66 stored rows x 34 half2 pairs.
// Stored row = logical row + 1 (rows 0 and 65 are guards).
// Pair q in plane p: lo accumulates col (2q-2+p) [wym&wyp taps], hi col (2q-1+p) [wy0].
#define PROWS 66
#define PPAIR 34
#define PS (PROWS * PPAIR)      // 2244 half2 per plane

// Scratch (zero at module load; the last block resets everything each replay)
__device__ float g_hist[NBATCH][NB * NB];
__device__ float g_total[NBATCH];
__device__ unsigned int g_ticket;

__global__ __launch_bounds__(THREADS) void mi_kernel(const float* __restrict__ x,
                                                     const float* __restrict__ y,
                                                     float* __restrict__ out) {
    __shared__ __half2 sh2[2 * PS];
    __shared__ float red_a[16], red_b[16];
    __shared__ float s_py[NB];
    __shared__ float s_res[NBATCH];
    __shared__ unsigned int s_last;
    const int n = blockIdx.y;
    const int t = threadIdx.x;
    const int lane = t & 31;
    const int w = t >> 5;

    for (int i = t; i < 2 * PS; i += THREADS) ((unsigned int*)sh2)[i] = 0u;
    __syncthreads();

    // K2 = DELTA^2/(2 sigma^2); constant scales dropped (cancel under norm).
    const float K2 = (float)( (1.0/63.0)*(1.0/63.0)
                     / (2.0 * (0.015625/2.3548200450309493) * (0.015625/2.3548200450309493)) );

    const float4* x4 = (const float4*)(x + (size_t)n * PPB);
    const float4* y4 = (const float4*)(y + (size_t)n * PPB);
    const int nvec = PPB / 4;
    const int stride = BPB * THREADS;

    for (int v = blockIdx.x * THREADS + t; v < nvec; v += stride) {
        float4 xv = x4[v];
        float4 yv = y4[v];
        float xs[4] = {xv.x, xv.y, xv.z, xv.w};
        float ys[4] = {yv.x, yv.y, yv.z, yv.w};
        #pragma unroll
        for (int e = 0; e < 4; e++) {
            float fx = xs[e] * 63.0f;
            int ix = __float2int_rn(fx);
            float ux = fx - (float)ix;
            float Ax = -K2 * ux * ux;
            float Bx = (2.0f * K2) * ux;
            float wx0 = __expf(Ax);
            float wxm = __expf(Ax - Bx - K2);
            float wxp = __expf(Ax + Bx - K2);
            float fy = ys[e] * 63.0f;
            int iy = __float2int_rn(fy);
            float uy = fy - (float)iy;
            float Ay = -K2 * uy * uy;
            float By = (2.0f * K2) * uy;
            float wy0 = __expf(Ay);
            float wym = __expf(Ay - By - K2);
            float wyp = __expf(Ay + By - K2);

            int par = iy & 1;
            int q0 = ((iy - 1) >> 1) + 1;              // 0..32
            int base = par * PS + ix * PPAIR + q0;     // guards absorb edges

            __half2 hy0 = __floats2half2_rn(wym, wy0);
            __half2 hy1 = __floats2half2_rn(wyp, 0.0f);
            __half2 hxm = __float2half2_rn(wxm);
            __half2 hx0 = __float2half2_rn(wx0);
            __half2 hxp = __float2half2_rn(wxp);

            atomicAdd(&sh2[base],               __hmul2(hxm, hy0));
            atomicAdd(&sh2[base + 1],           __hmul2(hxm, hy1));
            atomicAdd(&sh2[base + PPAIR],       __hmul2(hx0, hy0));
            atomicAdd(&sh2[base + PPAIR + 1],   __hmul2(hx0, hy1));
            atomicAdd(&sh2[base + 2*PPAIR],     __hmul2(hxp, hy0));
            atomicAdd(&sh2[base + 2*PPAIR + 1], __hmul2(hxp, hy1));
        }
    }

    __syncthreads();
    // ---- de-plane flush to global + block partial total (interior only) ----
    float s = 0.0f;
    for (int i = t; i < NB * NB; i += THREADS) {
        int r = i >> 6, c = i & 63;
        int sr = (r + 1) * PPAIR;
        float val;
        if (c & 1) {
            int q = (c + 1) >> 1;
            val = __low2float(sh2[sr + q]) + __high2float(sh2[PS + sr + q]);
        } else {
            val = __low2float(sh2[PS + sr + (c >> 1) + 1])
                + __high2float(sh2[sr + (c >> 1)]);
        }
        s += val;
        atomicAdd(&g_hist[n][i], val);
    }
    #pragma unroll
    for (int o = 16; o; o >>= 1) s += __shfl_down_sync(0xffffffffu, s, o);
    if (lane == 0) red_a[w] = s;
    __syncthreads();
    if (t == 0) {
        float tt = 0.0f;
        #pragma unroll
        for (int i = 0; i < 16; i++) tt += red_a[i];
        atomicAdd(&g_total[n], tt);
    }

    // ---- grid-wide ticket; last block finishes the reduction ----
    __threadfence();
    __syncthreads();
    if (t == 0) s_last = atomicInc(&g_ticket, TOTB - 1);   // wraps to 0
    __syncthreads();
    if (s_last != TOTB - 1) return;
    __threadfence();

    const float EPS = 1e-5f;
    for (int nn = 0; nn < NBATCH; nn++) {
        const float* h = g_hist[nn];
        const float inv = 1.0f / (g_total[nn] + EPS);
        if (t < NB) s_py[t] = 0.0f;
        if (t < 16) { red_a[t] = 0.0f; red_b[t] = 0.0f; }
        __syncthreads();

        // warps 0-7 do the entropy math (warp w owns rows [8w,8w+8))
        if (w < 8) {
            float ej = 0.0f, em = 0.0f, col0 = 0.0f, col1 = 0.0f;
            #pragma unroll
            for (int r8 = 0; r8 < 8; r8++) {
                int r = w * 8 + r8;
                float c0 = h[r * NB + lane];
                float c1 = h[r * NB + lane + 32];
                float p0 = c0 * inv, p1 = c1 * inv;
                ej += p0 * __logf(p0 + EPS) + p1 * __logf(p1 + EPS);
                col0 += c0; col1 += c1;
                float rs = c0 + c1;
                #pragma unroll
                for (int o = 16; o; o >>= 1) rs += __shfl_down_sync(0xffffffffu, rs, o);
                if (lane == 0) {
                    float px = rs * inv;
                    em += px * __logf(px + EPS);
                }
            }
            atomicAdd(&s_py[lane], col0);
            atomicAdd(&s_py[lane + 32], col1);
            #pragma unroll
            for (int o = 16; o; o >>= 1) ej += __shfl_down_sync(0xffffffffu, ej, o);
            if (lane == 0) { red_a[w] = ej; red_b[w] = em; }
        }
        __syncthreads();                 // s_py complete; red_a/red_b written

        // py entropy: t<64, warps 0-1
        float epy = 0.0f;
        if (t < NB) {
            float v = s_py[t] * inv;
            epy = v * __logf(v + EPS);
        }
        if (w < 2) {
            #pragma unroll
            for (int o = 16; o; o >>= 1) epy += __shfl_down_sync(0xffffffffu, epy, o);
        }
        __syncthreads();
        if (t == 0 || t == 32) s_py[w] = epy;    // reuse s_py[0..1] as scratch
        __syncthreads();

        if (t == 0) {
            float sej = 0.0f, sem = 0.0f;
            #pragma unroll
            for (int i = 0; i < 8; i++) { sej += red_a[i]; sem += red_b[i]; }
            float sepy = s_py[0] + s_py[1];
            s_res[nn] = (sem + sepy) / sej;      // (ent_x+ent_y)/ent_joint
            g_total[nn] = 0.0f;                  // reset for next replay
        }
        __syncthreads();                         // all reads of h done before zeroing

        // zero hist for next replay (all 16 warps share the work)
        for (int i = t; i < NB * NB; i += THREADS)
            ((float*)g_hist[nn])[i] = 0.0f;
        __syncthreads();
    }

    if (t == 0) out[0] = -0.5f * (s_res[0] + s_res[1]);
}

extern "C" void kernel_launch(void* const* d_in, const int* in_sizes, int n_in,
                              void* d_out, int out_size) {
    const float* x = (const float*)d_in[0];
    const float* y = (const float*)d_in[1];
    float* out = (float*)d_out;

    mi_kernel<<<dim3(BPB, NBATCH), THREADS>>>(x, y, out);
}

// round 11
// speedup vs baseline: 1.2020x; 1.0298x over previous
#include <cuda_runtime.h>
#include <cuda_fp16.h>

#define NBATCH 2
#define PPB (128*128*128)       // points per batch
#define NB 64
#define BPB 296                 // blocks per batch (4 blocks/SM, 256 thr: R8's proven geometry)
#define TOTB (BPB * NBATCH)     // 592
#define THREADS 256

// Plane layout: 2 parity planes, each 66 stored rows x 34 half2 pairs.
// Stored row = logical row + 1 (rows 0 and 65 are guards).
// Pair q in plane p: lo accumulates col (2q-2+p) [wym&wyp taps], hi col (2q-1+p) [wy0].
#define PROWS 66
#define PPAIR 34
#define PS (PROWS * PPAIR)      // 2244 half2 per plane

// Scratch (zero at module load; the last block resets everything each replay)
__device__ float g_hist[NBATCH][NB * NB];
__device__ float g_total[NBATCH];
__device__ unsigned int g_ticket;

__global__ __launch_bounds__(THREADS) void mi_kernel(const float* __restrict__ x,
                                                     const float* __restrict__ y,
                                                     float* __restrict__ out) {
    __shared__ __half2 sh2[2 * PS];
    __shared__ float red_a[8], red_b[8];
    __shared__ float s_py[NB];
    __shared__ float s_res[NBATCH];
    __shared__ unsigned int s_last;
    const int n = blockIdx.y;
    const int t = threadIdx.x;
    const int lane = t & 31;
    const int w = t >> 5;

    for (int i = t; i < 2 * PS; i += THREADS) ((unsigned int*)sh2)[i] = 0u;
    __syncthreads();

    // K2 = DELTA^2/(2 sigma^2); constant scales dropped (cancel under norm).
    const float K2 = (float)( (1.0/63.0)*(1.0/63.0)
                     / (2.0 * (0.015625/2.3548200450309493) * (0.015625/2.3548200450309493)) );

    const float4* x4 = (const float4*)(x + (size_t)n * PPB);
    const float4* y4 = (const float4*)(y + (size_t)n * PPB);
    const int nvec = PPB / 4;
    const int stride = BPB * THREADS;

    for (int v = blockIdx.x * THREADS + t; v < nvec; v += stride) {
        float4 xv = x4[v];
        float4 yv = y4[v];
        float xs[4] = {xv.x, xv.y, xv.z, xv.w};
        float ys[4] = {yv.x, yv.y, yv.z, yv.w};
        #pragma unroll
        for (int e = 0; e < 4; e++) {
            float fx = xs[e] * 63.0f;
            int ix = __float2int_rn(fx);
            float ux = fx - (float)ix;
            float Ax = -K2 * ux * ux;
            float Bx = (2.0f * K2) * ux;
            float wx0 = __expf(Ax);
            float wxm = __expf(Ax - Bx - K2);
            float wxp = __expf(Ax + Bx - K2);
            float fy = ys[e] * 63.0f;
            int iy = __float2int_rn(fy);
            float uy = fy - (float)iy;
            float Ay = -K2 * uy * uy;
            float By = (2.0f * K2) * uy;
            float wy0 = __expf(Ay);
            float wym = __expf(Ay - By - K2);
            float wyp = __expf(Ay + By - K2);

            int par = iy & 1;
            int q0 = ((iy - 1) >> 1) + 1;              // 0..32
            int base = par * PS + ix * PPAIR + q0;     // guards absorb edges

            __half2 hy0 = __floats2half2_rn(wym, wy0);
            __half2 hy1 = __floats2half2_rn(wyp, 0.0f);
            __half2 hxm = __float2half2_rn(wxm);
            __half2 hx0 = __float2half2_rn(wx0);
            __half2 hxp = __float2half2_rn(wxp);

            atomicAdd(&sh2[base],               __hmul2(hxm, hy0));
            atomicAdd(&sh2[base + 1],           __hmul2(hxm, hy1));
            atomicAdd(&sh2[base + PPAIR],       __hmul2(hx0, hy0));
            atomicAdd(&sh2[base + PPAIR + 1],   __hmul2(hx0, hy1));
            atomicAdd(&sh2[base + 2*PPAIR],     __hmul2(hxp, hy0));
            atomicAdd(&sh2[base + 2*PPAIR + 1], __hmul2(hxp, hy1));
        }
    }

    __syncthreads();
    // ---- de-plane flush to global + block partial total (interior only) ----
    float s = 0.0f;
    for (int i = t; i < NB * NB; i += THREADS) {
        int r = i >> 6, c = i & 63;
        int sr = (r + 1) * PPAIR;
        float val;
        if (c & 1) {
            int q = (c + 1) >> 1;
            val = __low2float(sh2[sr + q]) + __high2float(sh2[PS + sr + q]);
        } else {
            val = __low2float(sh2[PS + sr + (c >> 1) + 1])
                + __high2float(sh2[sr + (c >> 1)]);
        }
        s += val;
        atomicAdd(&g_hist[n][i], val);
    }
    #pragma unroll
    for (int o = 16; o; o >>= 1) s += __shfl_down_sync(0xffffffffu, s, o);
    if (lane == 0) red_a[w] = s;
    __syncthreads();
    if (t == 0) {
        float tt = 0.0f;
        #pragma unroll
        for (int i = 0; i < 8; i++) tt += red_a[i];
        atomicAdd(&g_total[n], tt);
    }

    // ---- grid-wide ticket; last block finishes the reduction ----
    __threadfence();
    __syncthreads();
    if (t == 0) s_last = atomicInc(&g_ticket, TOTB - 1);   // wraps to 0
    __syncthreads();
    if (s_last != TOTB - 1) return;
    __threadfence();

    const float EPS = 1e-5f;
    for (int nn = 0; nn < NBATCH; nn++) {
        const float* h = g_hist[nn];
        const float inv = 1.0f / (g_total[nn] + EPS);
        if (t < NB) s_py[t] = 0.0f;
        __syncthreads();

        // warp w owns rows [8w, 8w+8); lane owns cols lane & lane+32
        float ej = 0.0f, em = 0.0f, col0 = 0.0f, col1 = 0.0f;
        #pragma unroll
        for (int r8 = 0; r8 < 8; r8++) {
            int r = w * 8 + r8;
            float c0 = h[r * NB + lane];
            float c1 = h[r * NB + lane + 32];
            float p0 = c0 * inv, p1 = c1 * inv;
            ej += p0 * __logf(p0 + EPS) + p1 * __logf(p1 + EPS);
            col0 += c0; col1 += c1;
            float rs = c0 + c1;
            #pragma unroll
            for (int o = 16; o; o >>= 1) rs += __shfl_down_sync(0xffffffffu, rs, o);
            if (lane == 0) {
                float px = rs * inv;
                em += px * __logf(px + EPS);
            }
        }
        atomicAdd(&s_py[lane], col0);
        atomicAdd(&s_py[lane + 32], col1);
        #pragma unroll
        for (int o = 16; o; o >>= 1) ej += __shfl_down_sync(0xffffffffu, ej, o);
        if (lane == 0) { red_a[w] = ej; red_b[w] = em; }
        __syncthreads();                 // s_py complete; red_a/red_b written

        // py entropy: t<64, warps 0-1
        float epy = 0.0f;
        if (t < NB) {
            float v = s_py[t] * inv;
            epy = v * __logf(v + EPS);
        }
        #pragma unroll
        for (int o = 16; o; o >>= 1) epy += __shfl_down_sync(0xffffffffu, epy, o);
        if (lane == 0 && w < 2) s_py[w] = epy;   // reuse s_py[0..1] as scratch
        __syncthreads();

        if (t == 0) {
            float sej = 0.0f, sem = 0.0f;
            #pragma unroll
            for (int i = 0; i < 8; i++) { sej += red_a[i]; sem += red_b[i]; }
            float sepy = s_py[0] + s_py[1];
            s_res[nn] = (sem + sepy) / sej;      // (ent_x+ent_y)/ent_joint
            g_total[nn] = 0.0f;                  // reset for next replay
        }

        // zero own rows for next replay (each warp read only its own rows)
        #pragma unroll
        for (int r8 = 0; r8 < 8; r8++) {
            int r = w * 8 + r8;
            ((float*)g_hist[nn])[r * NB + lane] = 0.0f;
            ((float*)g_hist[nn])[r * NB + lane + 32] = 0.0f;
        }
        __syncthreads();
    }

    if (t == 0) out[0] = -0.5f * (s_res[0] + s_res[1]);
}

extern "C" void kernel_launch(void* const* d_in, const int* in_sizes, int n_in,
                              void* d_out, int out_size) {
    const float* x = (const float*)d_in[0];
    const float* y = (const float*)d_in[1];
    float* out = (float*)d_out;

    mi_kernel<<<dim3(BPB, NBATCH), THREADS>>>(x, y, out);
}

// round 12
// speedup vs baseline: 1.2880x; 1.0716x over previous
#include <cuda_runtime.h>
#include <cuda_fp16.h>

#define NBATCH 2
#define PPB (128*128*128)       // points per batch
#define NB 64
#define BLOCKS_PER_BATCH 296   // 592 blocks total, 4/SM: proven hist geometry
#define THREADS 256

// Plane layout: 2 parity planes, each 66 stored rows x 34 half2 pairs.
// Stored row = logical row + 1 (rows 0 and 65 are guards).
// Pair q in plane p: lo accumulates col (2q-2+p) [wym&wyp taps], hi col (2q-1+p) [wy0].
#define PROWS 66
#define PPAIR 34
#define PS (PROWS * PPAIR)      // 2244 half2 per plane

// Scratch (zero at module load; finalize resets everything each replay)
__device__ float g_hist[NBATCH][NB * NB];
__device__ float g_total[NBATCH];

__global__ __launch_bounds__(THREADS) void hist_kernel(const float* __restrict__ x,
                                                       const float* __restrict__ y,
                                                       float* __restrict__ out) {
    __shared__ __half2 sh2[2 * PS];
    __shared__ float red[8];
    const int n = blockIdx.y;
    const int t = threadIdx.x;

    // zero the output accumulator once per launch (kernel boundary orders this
    // before finalize's atomicAdds; re-done every graph replay)
    if (blockIdx.x == 0 && n == 0 && t == 0) out[0] = 0.0f;

    for (int i = t; i < 2 * PS; i += THREADS) ((unsigned int*)sh2)[i] = 0u;
    __syncthreads();

    // K2 = DELTA^2/(2 sigma^2); constant scales dropped (cancel under norm).
    const float K2 = (float)( (1.0/63.0)*(1.0/63.0)
                     / (2.0 * (0.015625/2.3548200450309493) * (0.015625/2.3548200450309493)) );

    const float4* x4 = (const float4*)(x + (size_t)n * PPB);
    const float4* y4 = (const float4*)(y + (size_t)n * PPB);
    const int nvec = PPB / 4;
    const int stride = BLOCKS_PER_BATCH * THREADS;

    for (int v = blockIdx.x * THREADS + t; v < nvec; v += stride) {
        float4 xv = x4[v];
        float4 yv = y4[v];
        float xs[4] = {xv.x, xv.y, xv.z, xv.w};
        float ys[4] = {yv.x, yv.y, yv.z, yv.w};
        #pragma unroll
        for (int e = 0; e < 4; e++) {
            float fx = xs[e] * 63.0f;
            int ix = __float2int_rn(fx);
            float ux = fx - (float)ix;
            float Ax = -K2 * ux * ux;
            float Bx = (2.0f * K2) * ux;
            float wx0 = __expf(Ax);
            float wxm = __expf(Ax - Bx - K2);
            float wxp = __expf(Ax + Bx - K2);
            float fy = ys[e] * 63.0f;
            int iy = __float2int_rn(fy);
            float uy = fy - (float)iy;
            float Ay = -K2 * uy * uy;
            float By = (2.0f * K2) * uy;
            float wy0 = __expf(Ay);
            float wym = __expf(Ay - By - K2);
            float wyp = __expf(Ay + By - K2);

            int par = iy & 1;
            int q0 = ((iy - 1) >> 1) + 1;              // 0..32
            int base = par * PS + ix * PPAIR + q0;     // guards absorb edges

            __half2 hy0 = __floats2half2_rn(wym, wy0);
            __half2 hy1 = __floats2half2_rn(wyp, 0.0f);
            __half2 hxm = __float2half2_rn(wxm);
            __half2 hx0 = __float2half2_rn(wx0);
            __half2 hxp = __float2half2_rn(wxp);

            atomicAdd(&sh2[base],               __hmul2(hxm, hy0));
            atomicAdd(&sh2[base + 1],           __hmul2(hxm, hy1));
            atomicAdd(&sh2[base + PPAIR],       __hmul2(hx0, hy0));
            atomicAdd(&sh2[base + PPAIR + 1],   __hmul2(hx0, hy1));
            atomicAdd(&sh2[base + 2*PPAIR],     __hmul2(hxp, hy0));
            atomicAdd(&sh2[base + 2*PPAIR + 1], __hmul2(hxp, hy1));
        }
    }

    __syncthreads();
    // ---- de-plane flush to global + block partial total (interior only) ----
    float s = 0.0f;
    for (int i = t; i < NB * NB; i += THREADS) {
        int r = i >> 6, c = i & 63;
        int sr = (r + 1) * PPAIR;
        float val;
        if (c & 1) {
            int q = (c + 1) >> 1;
            val = __low2float(sh2[sr + q]) + __high2float(sh2[PS + sr + q]);
        } else {
            val = __low2float(sh2[PS + sr + (c >> 1) + 1])
                + __high2float(sh2[sr + (c >> 1)]);
        }
        s += val;
        atomicAdd(&g_hist[n][i], val);
    }
    #pragma unroll
    for (int o = 16; o; o >>= 1) s += __shfl_down_sync(0xffffffffu, s, o);
    if ((t & 31) == 0) red[t >> 5] = s;
    __syncthreads();
    if (t == 0) {
        float tt = 0.0f;
        #pragma unroll
        for (int i = 0; i < 8; i++) tt += red[i];
        atomicAdd(&g_total[n], tt);
    }
}

// grid = 2 blocks (one per batch), 1024 threads. Thread t owns the float4 at
// row r = t>>4, cols 4k..4k+3 (k = t&15). Single pass; no inter-block ticket.
__global__ __launch_bounds__(1024) void finalize_kernel(float* __restrict__ out) {
    __shared__ float s_py[NB];
    __shared__ float red_ej[32], red_em[32];
    const float EPS = 1e-5f;
    const int n = blockIdx.x;
    const int t = threadIdx.x;
    const int lane = t & 31;
    const int w = t >> 5;
    float* h = g_hist[n];
    const float inv = 1.0f / (g_total[n] + EPS);

    if (t < NB) s_py[t] = 0.0f;
    __syncthreads();

    const int r = t >> 4, k = t & 15;
    float4 c = *(const float4*)(h + r * NB + k * 4);

    // joint entropy partial (4 cells)
    float p0 = c.x * inv, p1 = c.y * inv, p2 = c.z * inv, p3 = c.w * inv;
    float ej = p0 * __logf(p0 + EPS) + p1 * __logf(p1 + EPS)
             + p2 * __logf(p2 + EPS) + p3 * __logf(p3 + EPS);

    // column partials -> s_py (spread shared atomics)
    atomicAdd(&s_py[k * 4 + 0], c.x);
    atomicAdd(&s_py[k * 4 + 1], c.y);
    atomicAdd(&s_py[k * 4 + 2], c.z);
    atomicAdd(&s_py[k * 4 + 3], c.w);

    // row sum across the 16 threads of row r (width-16 shuffle groups)
    float rs = c.x + c.y + c.z + c.w;
    rs += __shfl_down_sync(0xffffffffu, rs, 8, 16);
    rs += __shfl_down_sync(0xffffffffu, rs, 4, 16);
    rs += __shfl_down_sync(0xffffffffu, rs, 2, 16);
    rs += __shfl_down_sync(0xffffffffu, rs, 1, 16);
    float em = 0.0f;
    if (k == 0) {                       // lanes 0 and 16 hold a full row sum
        float px = rs * inv;
        em = px * __logf(px + EPS);
    }

    // zero own cells for next replay (each thread zeroes exactly what it read)
    *(float4*)(h + r * NB + k * 4) = make_float4(0.f, 0.f, 0.f, 0.f);

    // warp-reduce ej and em
    #pragma unroll
    for (int o = 16; o; o >>= 1) {
        ej += __shfl_down_sync(0xffffffffu, ej, o);
        em += __shfl_down_sync(0xffffffffu, em, o);
    }
    if (lane == 0) { red_ej[w] = ej; red_em[w] = em; }
    __syncthreads();                    // s_py atomics + red arrays complete

    // py entropy (t < 64)
    float epy = 0.0f;
    if (t < NB) {
        float v = s_py[t] * inv;
        epy = v * __logf(v + EPS);
    }
    #pragma unroll
    for (int o = 16; o; o >>= 1) epy += __shfl_down_sync(0xffffffffu, epy, o);
    __syncthreads();                    // all s_py reads done before reuse
    if (lane == 0 && w < 2) s_py[w] = epy;   // scratch reuse
    __syncthreads();

    if (w == 0) {
        float a = red_ej[lane];
        float b = red_em[lane];
        #pragma unroll
        for (int o = 16; o; o >>= 1) {
            a += __shfl_down_sync(0xffffffffu, a, o);
            b += __shfl_down_sync(0xffffffffu, b, o);
        }
        if (lane == 0) {
            float sepy = s_py[0] + s_py[1];
            // ent_xy = -(b + sepy); ent_joint = -a; ratio = (b+sepy)/a
            atomicAdd(out, -0.5f * ((b + sepy) / a));
            g_total[n] = 0.0f;          // reset for next replay
        }
    }
}

extern "C" void kernel_launch(void* const* d_in, const int* in_sizes, int n_in,
                              void* d_out, int out_size) {
    const float* x = (const float*)d_in[0];
    const float* y = (const float*)d_in[1];
    float* out = (float*)d_out;

    hist_kernel<<<dim3(BLOCKS_PER_BATCH, NBATCH), THREADS>>>(x, y, out);
    finalize_kernel<<<NBATCH, 1024>>>(out);
}

// round 13
// speedup vs baseline: 1.3553x; 1.0523x over previous
#include <cuda_runtime.h>
#include <cuda_fp16.h>

#define NBATCH 2
#define PPB (128*128*128)       // points per batch
#define NB 64
#define BLOCKS_PER_BATCH 296   // 592 blocks total, 4/SM: proven hist geometry
#define THREADS 256
#define FBLK 8                 // finalize1 blocks per batch

// Plane layout: 2 parity planes, each 66 stored rows x 34 half2 pairs.
// Stored row = logical row + 1 (rows 0 and 65 are guards).
// Pair q in plane p: lo accumulates col (2q-2+p) [wym&wyp taps], hi col (2q-1+p) [wy0].
#define PROWS 66
#define PPAIR 34
#define PS (PROWS * PPAIR)      // 2244 half2 per plane

// Scratch (zero at module load; finalize stages reset everything each replay)
__device__ float g_hist[NBATCH][NB * NB];
__device__ float g_total[NBATCH];
__device__ float g_py[NBATCH][NB];
__device__ float g_ej[NBATCH];
__device__ float g_em[NBATCH];

__global__ __launch_bounds__(THREADS) void hist_kernel(const float* __restrict__ x,
                                                       const float* __restrict__ y) {
    __shared__ __half2 sh2[2 * PS];
    __shared__ float red[8];
    const int n = blockIdx.y;
    const int t = threadIdx.x;

    for (int i = t; i < 2 * PS; i += THREADS) ((unsigned int*)sh2)[i] = 0u;
    __syncthreads();

    // K2 = DELTA^2/(2 sigma^2); constant scales dropped (cancel under norm).
    const float K2 = (float)( (1.0/63.0)*(1.0/63.0)
                     / (2.0 * (0.015625/2.3548200450309493) * (0.015625/2.3548200450309493)) );

    const float4* x4 = (const float4*)(x + (size_t)n * PPB);
    const float4* y4 = (const float4*)(y + (size_t)n * PPB);
    const int nvec = PPB / 4;
    const int stride = BLOCKS_PER_BATCH * THREADS;

    for (int v = blockIdx.x * THREADS + t; v < nvec; v += stride) {
        float4 xv = x4[v];
        float4 yv = y4[v];
        float xs[4] = {xv.x, xv.y, xv.z, xv.w};
        float ys[4] = {yv.x, yv.y, yv.z, yv.w};
        #pragma unroll
        for (int e = 0; e < 4; e++) {
            float fx = xs[e] * 63.0f;
            int ix = __float2int_rn(fx);
            float ux = fx - (float)ix;
            float Ax = -K2 * ux * ux;
            float Bx = (2.0f * K2) * ux;
            float wx0 = __expf(Ax);
            float wxm = __expf(Ax - Bx - K2);
            float wxp = __expf(Ax + Bx - K2);
            float fy = ys[e] * 63.0f;
            int iy = __float2int_rn(fy);
            float uy = fy - (float)iy;
            float Ay = -K2 * uy * uy;
            float By = (2.0f * K2) * uy;
            float wy0 = __expf(Ay);
            float wym = __expf(Ay - By - K2);
            float wyp = __expf(Ay + By - K2);

            int par = iy & 1;
            int q0 = ((iy - 1) >> 1) + 1;              // 0..32
            int base = par * PS + ix * PPAIR + q0;     // guards absorb edges

            __half2 hy0 = __floats2half2_rn(wym, wy0);
            __half2 hy1 = __floats2half2_rn(wyp, 0.0f);
            __half2 hxm = __float2half2_rn(wxm);
            __half2 hx0 = __float2half2_rn(wx0);
            __half2 hxp = __float2half2_rn(wxp);

            atomicAdd(&sh2[base],               __hmul2(hxm, hy0));
            atomicAdd(&sh2[base + 1],           __hmul2(hxm, hy1));
            atomicAdd(&sh2[base + PPAIR],       __hmul2(hx0, hy0));
            atomicAdd(&sh2[base + PPAIR + 1],   __hmul2(hx0, hy1));
            atomicAdd(&sh2[base + 2*PPAIR],     __hmul2(hxp, hy0));
            atomicAdd(&sh2[base + 2*PPAIR + 1], __hmul2(hxp, hy1));
        }
    }

    __syncthreads();
    // ---- de-plane flush to global + block partial total (interior only) ----
    float s = 0.0f;
    for (int i = t; i < NB * NB; i += THREADS) {
        int r = i >> 6, c = i & 63;
        int sr = (r + 1) * PPAIR;
        float val;
        if (c & 1) {
            int q = (c + 1) >> 1;
            val = __low2float(sh2[sr + q]) + __high2float(sh2[PS + sr + q]);
        } else {
            val = __low2float(sh2[PS + sr + (c >> 1) + 1])
                + __high2float(sh2[sr + (c >> 1)]);
        }
        s += val;
        atomicAdd(&g_hist[n][i], val);
    }
    #pragma unroll
    for (int o = 16; o; o >>= 1) s += __shfl_down_sync(0xffffffffu, s, o);
    if ((t & 31) == 0) red[t >> 5] = s;
    __syncthreads();
    if (t == 0) {
        float tt = 0.0f;
        #pragma unroll
        for (int i = 0; i < 8; i++) tt += red[i];
        atomicAdd(&g_total[n], tt);
    }
}

// Stage 1: grid = NBATCH*FBLK blocks x 256 thr. Block (n,b) owns rows [8b,8b+8).
// Joint-entropy partial -> g_ej, row entropies -> g_em, col partials -> g_py,
// then zeroes its slice. No cross-block dependency.
__global__ __launch_bounds__(256) void finalize1_kernel() {
    __shared__ float red[8];
    const float EPS = 1e-5f;
    const int n = blockIdx.x >> 3;
    const int b = blockIdx.x & 7;
    float* h = g_hist[n] + b * 8 * NB;      // 512 cells
    const float inv = 1.0f / (g_total[n] + EPS);
    const int t = threadIdx.x;
    const int lane = t & 31;
    const int w = t >> 5;                   // warp = local row

    float c0 = h[w * NB + lane];
    float c1 = h[w * NB + lane + 32];

    // joint entropy partial
    float p0 = c0 * inv, p1 = c1 * inv;
    float ej = p0 * __logf(p0 + EPS) + p1 * __logf(p1 + EPS);
    #pragma unroll
    for (int o = 16; o; o >>= 1) ej += __shfl_down_sync(0xffffffffu, ej, o);

    // row sum (px): warp w owns row w -> entropy contribution is block-local
    float rs = c0 + c1;
    #pragma unroll
    for (int o = 16; o; o >>= 1) rs += __shfl_down_sync(0xffffffffu, rs, o);
    float em = 0.0f;
    if (lane == 0) {
        float px = rs * inv;
        em = px * __logf(px + EPS);
        red[w] = ej;
    }
    __syncthreads();
    if (t == 0) {
        float e = 0.0f;
        #pragma unroll
        for (int i = 0; i < 8; i++) e += red[i];
        atomicAdd(&g_ej[n], e);
    }
    if (lane == 0) atomicAdd(&g_em[n], em);

    // column partials (normalized) over this block's 8 rows
    if (t < NB) {
        float cs = 0.0f;
        #pragma unroll
        for (int r = 0; r < 8; r++) cs += h[r * NB + t];
        atomicAdd(&g_py[n][t], cs * inv);
    }

    // BARRIER: py loop (warps 0-1) reads ALL rows of this slice before zeroing.
    __syncthreads();
    h[w * NB + lane] = 0.0f;
    h[w * NB + lane + 32] = 0.0f;
}

// Stage 2: 1 block x 128 threads. py entropies + combine + reset scalars.
__global__ __launch_bounds__(128) void finalize2_kernel(float* __restrict__ out) {
    __shared__ float pw[4];
    const float EPS = 1e-5f;
    const int t = threadIdx.x;
    const int lane = t & 31;
    const int w = t >> 5;                   // warps 0-1: batch0, 2-3: batch1

    const int nn = t >> 6, c = t & 63;
    float v = g_py[nn][c];
    float e = v * __logf(v + EPS);
    g_py[nn][c] = 0.0f;                     // reset for next replay

    #pragma unroll
    for (int o = 16; o; o >>= 1) e += __shfl_down_sync(0xffffffffu, e, o);
    if (lane == 0) pw[w] = e;
    __syncthreads();

    if (t == 0) {
        float epy0 = pw[0] + pw[1];
        float epy1 = pw[2] + pw[3];
        float r0 = (g_em[0] + epy0) / g_ej[0];
        float r1 = (g_em[1] + epy1) / g_ej[1];
        out[0] = -0.5f * (r0 + r1);
        g_em[0] = g_em[1] = 0.0f;
        g_ej[0] = g_ej[1] = 0.0f;
        g_total[0] = g_total[1] = 0.0f;
    }
}

extern "C" void kernel_launch(void* const* d_in, const int* in_sizes, int n_in,
                              void* d_out, int out_size) {
    const float* x = (const float*)d_in[0];
    const float* y = (const float*)d_in[1];
    float* out = (float*)d_out;

    hist_kernel<<<dim3(BLOCKS_PER_BATCH, NBATCH), THREADS>>>(x, y);
    finalize1_kernel<<<NBATCH * FBLK, 256>>>();
    finalize2_kernel<<<1, 128>>>(out);
}